// round 17
// baseline (speedup 1.0000x reference)
#include <cuda_runtime.h>
#include <cuda_fp16.h>
#include <cstdint>

#define N_VOX    100000
#define NK       27
#define LN_EPS   1e-5f
#define NTHREADS 256
#define TILE_M   128
#define GRID_M   ((N_VOX + TILE_M - 1) / TILE_M)   // 782

// smem stage: A 128x(64+8 pad) fp16 = 18432B ; W 64x(64+8) fp16 = 9216B
#define ROWB    144                      // row stride bytes (72 fp16)
#define A_BYTES 18432
#define STAGE   27648
#define SMEM_BYTES (2 * STAGE)           // 55296 -> 3 CTAs/SM (24 warps)

// Precomputed fp16 data (static device globals, no allocation)
__device__ __align__(16) __half g_f16[N_VOX * 64];
__device__ __align__(16) __half g_w16[28 * 4096];   // [tap][cout][cin], tap27 = W_lin

// ---------- helpers ----------
__device__ __forceinline__ uint32_t smem_u32(const void* p) {
    uint32_t a;
    asm("{ .reg .u64 t; cvta.to.shared.u64 t, %1; cvt.u32.u64 %0, t; }" : "=r"(a) : "l"(p));
    return a;
}
__device__ __forceinline__ uint32_t lds32(uint32_t a) {
    uint32_t v;
    asm volatile("ld.shared.b32 %0, [%1];" : "=r"(v) : "r"(a));
    return v;
}
__device__ __forceinline__ void sts32(uint32_t a, uint32_t v) {
    asm volatile("st.shared.b32 [%0], %1;" :: "r"(a), "r"(v));
}
__device__ __forceinline__ void cpa16(uint32_t dst, const void* src) {
    asm volatile("cp.async.cg.shared.global [%0], [%1], 16;" :: "r"(dst), "l"(src));
}
#define CP_COMMIT()  asm volatile("cp.async.commit_group;" ::: "memory")
#define CP_WAIT(n)   asm volatile("cp.async.wait_group %0;" :: "n"(n) : "memory")

__device__ __forceinline__ void mma16816(float* c, const uint32_t* a,
                                         uint32_t b0, uint32_t b1) {
    asm volatile(
        "mma.sync.aligned.m16n8k16.row.col.f32.f16.f16.f32 "
        "{%0,%1,%2,%3}, {%4,%5,%6,%7}, {%8,%9}, {%0,%1,%2,%3};"
        : "+f"(c[0]), "+f"(c[1]), "+f"(c[2]), "+f"(c[3])
        : "r"(a[0]), "r"(a[1]), "r"(a[2]), "r"(a[3]), "r"(b0), "r"(b1));
}

// ---------- merged pre-kernel ----------
#define FEAT_BLOCKS 3125                 // N_VOX*8 / 256
#define W_BLOCKS    448                  // 28*4096 / 256

__global__ void prep_all(const float* __restrict__ feats,
                         const float* __restrict__ Wc, const float* __restrict__ Wl) {
    int b = blockIdx.x;
    if (b < FEAT_BLOCKS) {
        int t = b * blockDim.x + threadIdx.x;      // 8 floats / thread
        if (t >= N_VOX * 8) return;
        const float4* F = (const float4*)feats;
        float4 f0 = F[t * 2], f1 = F[t * 2 + 1];
        __half2 h0 = __floats2half2_rn(f0.x, f0.y);
        __half2 h1 = __floats2half2_rn(f0.z, f0.w);
        __half2 h2 = __floats2half2_rn(f1.x, f1.y);
        __half2 h3 = __floats2half2_rn(f1.z, f1.w);
        uint4 o;
        o.x = *(uint32_t*)&h0; o.y = *(uint32_t*)&h1;
        o.z = *(uint32_t*)&h2; o.w = *(uint32_t*)&h3;
        ((uint4*)g_f16)[t] = o;
    } else {
        int e = (b - FEAT_BLOCKS) * blockDim.x + threadIdx.x;   // (tap, o, c)
        if (e >= 28 * 4096) return;
        int k = e >> 12, rem = e & 4095;
        int o = rem >> 6, c = rem & 63;
        float w = (k < 27) ? Wc[k * 4096 + c * 64 + o] : Wl[c * 64 + o];
        g_w16[e] = __float2half_rn(w);
    }
}

// ---------- main: 256 threads, M=128 tile, 8 warps x m16n64 ----------
__global__ __launch_bounds__(NTHREADS, 3)
void conv_mma_kernel(const int* __restrict__ nb, const float* __restrict__ bc,
                     const float* __restrict__ bl, const float* __restrict__ gamma,
                     const float* __restrict__ beta, float* __restrict__ out)
{
    extern __shared__ __align__(16) char smem[];
    const uint32_t sb = smem_u32(smem);
    const int tid  = threadIdx.x;
    const int lane = tid & 31;
    const int w    = tid >> 5;       // 0..7 -> rows [w*16, w*16+16)
    const int group = lane >> 2;     // 0..7
    const int qp    = lane & 3;      // 0..3
    // gather role: each PAIR of threads loads one A row (4 chunks each)
    const int arow_g = tid >> 1;     // 0..127
    const int ahalf  = tid & 1;      // 0/1 -> 64B half of the row
    const int gv_row = blockIdx.x * TILE_M + arow_g;
    const bool row_act = gv_row < N_VOX;
    const int* nrowA = nb + (long)gv_row * NK;

    float c[8][4];
    #pragma unroll
    for (int nt = 0; nt < 8; nt++)
        #pragma unroll
        for (int r = 0; r < 4; r++) c[nt][r] = 0.0f;

    // ---- issue helpers ----
    auto issueA = [&](int s, int k) {
        uint32_t dst = sb + s * STAGE + arow_g * ROWB + ahalf * 64;
        int idx = row_act ? nrowA[k] : -1;
        if (idx >= 0) {
            const char* src = (const char*)(g_f16 + (size_t)idx * 64) + ahalf * 64;
            #pragma unroll
            for (int j = 0; j < 4; j++) cpa16(dst + j * 16, src + j * 16);
        } else {
            float4 z = make_float4(0.f, 0.f, 0.f, 0.f);
            char* d = smem + s * STAGE + arow_g * ROWB + ahalf * 64;
            #pragma unroll
            for (int j = 0; j < 4; j++) *(float4*)(d + j * 16) = z;
        }
    };
    auto issueW = [&](uint32_t wbase, int k) {
        const char* srcb = (const char*)(g_w16 + (size_t)k * 4096);
        #pragma unroll
        for (int t = 0; t < 2; t++) {
            int ch = tid + t * NTHREADS;     // 512 chunks of 16B
            int row = ch >> 3, j = ch & 7;
            cpa16(wbase + row * ROWB + j * 16, srcb + ch * 16);
        }
    };

    // Pipelined m16n64 tap GEMM
    auto do_tap = [&](uint32_t Ab, uint32_t Wb) {
        const uint32_t arow0 = Ab + (w * 16 + group) * ROWB + qp * 4;
        const uint32_t brow  = Wb + group * ROWB + qp * 4;
        uint32_t a_cur[4], a_nxt[4];
        a_cur[0] = lds32(arow0);
        a_cur[1] = lds32(arow0 + 8 * ROWB);
        a_cur[2] = lds32(arow0 + 16);
        a_cur[3] = lds32(arow0 + 8 * ROWB + 16);
        #pragma unroll
        for (int k4 = 0; k4 < 4; k4++) {
            const int koff = k4 * 32;
            if (k4 < 3) {
                uint32_t base = arow0 + koff + 32;
                a_nxt[0] = lds32(base);
                a_nxt[1] = lds32(base + 8 * ROWB);
                a_nxt[2] = lds32(base + 16);
                a_nxt[3] = lds32(base + 8 * ROWB + 16);
            }
            uint32_t bn0 = lds32(brow + koff);
            uint32_t bn1 = lds32(brow + koff + 16);
            #pragma unroll
            for (int nt = 0; nt < 8; nt++) {
                uint32_t b0 = bn0, b1 = bn1;
                if (nt < 7) {
                    uint32_t baddr = brow + (nt + 1) * 8 * ROWB + koff;
                    bn0 = lds32(baddr);
                    bn1 = lds32(baddr + 16);
                }
                mma16816(c[nt], a_cur, b0, b1);
            }
            if (k4 < 3) {
                #pragma unroll
                for (int r = 0; r < 4; r++) a_cur[r] = a_nxt[r];
            }
        }
    };

    // ---- prologue: taps 0,1 ----
    issueA(0, 0); issueW(sb + 0 * STAGE + A_BYTES, 0); CP_COMMIT();
    issueA(1, 1); issueW(sb + 1 * STAGE + A_BYTES, 1); CP_COMMIT();

    // ---- conv mainloop ----
    #pragma unroll 1
    for (int k = 0; k < NK; k++) {
        const int s = k & 1;
        if (k < NK - 1) CP_WAIT(1); else CP_WAIT(0);
        __syncthreads();
        do_tap(sb + s * STAGE, sb + s * STAGE + A_BYTES);
        __syncthreads();
        if (k + 2 < NK) {
            issueA(s, k + 2);
            issueW(sb + s * STAGE + A_BYTES, k + 2);
            CP_COMMIT();
        }
    }

    // ---- epilogue: +bc, convert to fp16 X in stage0 A; load W_lin ----
    issueW(sb + A_BYTES, 27); CP_COMMIT();
    {
        const int r0 = w * 16 + group;
        #pragma unroll
        for (int nt = 0; nt < 8; nt++) {
            const int col0 = nt * 8 + qp * 2;
            const float b0 = bc[col0], b1 = bc[col0 + 1];
            float x0 = c[nt][0] + b0;
            float x1 = c[nt][1] + b1;
            float x2 = c[nt][2] + b0;
            float x3 = c[nt][3] + b1;
            __half2 p0 = __floats2half2_rn(x0, x1);
            __half2 p1 = __floats2half2_rn(x2, x3);
            sts32(sb + r0 * ROWB + col0 * 2, *(uint32_t*)&p0);
            sts32(sb + (r0 + 8) * ROWB + col0 * 2, *(uint32_t*)&p1);
        }
    }
    CP_WAIT(0);
    __syncthreads();

    // ---- linear GEMM (tap 27) ----
    #pragma unroll
    for (int nt = 0; nt < 8; nt++)
        #pragma unroll
        for (int r = 0; r < 4; r++) c[nt][r] = 0.0f;
    do_tap(sb, sb + A_BYTES);

    // ---- +bl, layernorm in registers ----
    float sum[2] = {0.f, 0.f};
    float sq [2] = {0.f, 0.f};
    #pragma unroll
    for (int nt = 0; nt < 8; nt++) {
        const int col0 = nt * 8 + qp * 2;
        const float b0 = bl[col0], b1 = bl[col0 + 1];
        float y0 = c[nt][0] + b0, y1 = c[nt][1] + b1;
        float y2 = c[nt][2] + b0, y3 = c[nt][3] + b1;
        c[nt][0] = y0; c[nt][1] = y1;
        c[nt][2] = y2; c[nt][3] = y3;
        sum[0] += y0 + y1;  sq[0] += y0 * y0 + y1 * y1;
        sum[1] += y2 + y3;  sq[1] += y2 * y2 + y3 * y3;
    }
    #pragma unroll
    for (int off = 1; off <= 2; off <<= 1) {
        #pragma unroll
        for (int h = 0; h < 2; h++) {
            sum[h] += __shfl_xor_sync(0xffffffffu, sum[h], off);
            sq [h] += __shfl_xor_sync(0xffffffffu, sq [h], off);
        }
    }
    float mu[2], rs[2];
    #pragma unroll
    for (int h = 0; h < 2; h++) {
        float m = sum[h] * (1.0f / 64.0f);
        float v = sq[h] * (1.0f / 64.0f) - m * m;
        mu[h] = m;
        rs[h] = rsqrtf(v + LN_EPS);
    }
    const int base_row = blockIdx.x * TILE_M + w * 16 + group;
    #pragma unroll
    for (int nt = 0; nt < 8; nt++) {
        const int col0 = nt * 8 + qp * 2;
        const float g0 = gamma[col0], g1 = gamma[col0 + 1];
        const float be0 = beta[col0], be1 = beta[col0 + 1];
        int r0 = base_row;
        int r1 = base_row + 8;
        if (r0 < N_VOX) {
            float2 o;
            o.x = g0 * (c[nt][0] - mu[0]) * rs[0] + be0;
            o.y = g1 * (c[nt][1] - mu[0]) * rs[0] + be1;
            *(float2*)(out + (size_t)r0 * 64 + col0) = o;
        }
        if (r1 < N_VOX) {
            float2 o;
            o.x = g0 * (c[nt][2] - mu[1]) * rs[1] + be0;
            o.y = g1 * (c[nt][3] - mu[1]) * rs[1] + be1;
            *(float2*)(out + (size_t)r1 * 64 + col0) = o;
        }
    }
}

// ---------- launch ----------
extern "C" void kernel_launch(void* const* d_in, const int* in_sizes, int n_in,
                              void* d_out, int out_size)
{
    const float* feats = (const float*)d_in[0];
    const int*   nb    = (const int*)d_in[1];
    const float* Wc    = (const float*)d_in[2];
    const float* bc    = (const float*)d_in[3];
    const float* Wl    = (const float*)d_in[4];
    const float* bl    = (const float*)d_in[5];
    const float* gamma = (const float*)d_in[6];
    const float* beta  = (const float*)d_in[7];
    float* out = (float*)d_out;

    static int init = 0;
    if (!init) {
        cudaFuncSetAttribute(conv_mma_kernel,
                             cudaFuncAttributeMaxDynamicSharedMemorySize, SMEM_BYTES);
        init = 1;
    }
    prep_all<<<FEAT_BLOCKS + W_BLOCKS, 256>>>(feats, Wc, Wl);
    conv_mma_kernel<<<GRID_M, NTHREADS, SMEM_BYTES>>>(nb, bc, bl, gamma, beta, out);
}